// round 6
// baseline (speedup 1.0000x reference)
#include <cuda_runtime.h>
#include <cstdint>

// VoxelHashTable: 2-level voxel hash trilinear interpolation.
// 16 lanes per QUERY: lane k = (level = k>>3, corner = k&7).
//   - each lane: ONE h2v lookup (its corner, its level), its level's
//     floor/frac/weight math only
//   - broadcast: 8 shfl(width=16) steps; src lane (k&8)|c serves both
//     levels simultaneously
//   - gather: per step, lanes 0-7 fetch the level0 row, lanes 8-15 the
//     level1 row; each 8-lane half reads one full 128B feats row
//     (16B/lane) = 1 coalesced L1 wavefront
//   - store: warp covers 2 queries x 64 floats contiguous, fully coalesced
//
// Inputs (metadata order):
//   d_in[0] query_pts : float32 (M*3)
//   d_in[1] feats0    : float32 (n0*32)
//   d_in[2] feats1    : float32 (n1*32)
//   d_in[3] h2v0      : int32   (2^20)
//   d_in[4] h2v1      : int32   (2^20)
// Output: float32 (M*64) = concat(level0, level1)

#define TSIZE 1048576u
#define TMASK (TSIZE - 1u)

__device__ __forceinline__ constexpr unsigned P0() { return 73856093u % TSIZE; }
__device__ __forceinline__ constexpr unsigned P1() { return 19349669u % TSIZE; }
__device__ __forceinline__ constexpr unsigned P2() { return 83492791u % TSIZE; }

__global__ void
voxel_hash_kernel(const float* __restrict__ qpts,
                  const float* __restrict__ feats0,
                  const float* __restrict__ feats1,
                  const int*   __restrict__ h2v0,
                  const int*   __restrict__ h2v1,
                  float*       __restrict__ out,
                  int M)
{
    int t      = blockIdx.x * blockDim.x + threadIdx.x;
    int qi     = t >> 4;          // query id; grid divides exactly
    int lane16 = t & 15;
    int lane8  = lane16 & 7;      // corner id == feature-chunk id
    int lvl    = lane16 >> 3;     // level id

    const float inv_res            = lvl ? (1.0f / 0.24f) : (1.0f / 0.12f);
    const float* __restrict__ feats = lvl ? feats1 : feats0;
    const int*   __restrict__ h2v   = lvl ? h2v1   : h2v0;

    float qx = __ldg(&qpts[qi * 3 + 0]);
    float qy = __ldg(&qpts[qi * 3 + 1]);
    float qz = __ldg(&qpts[qi * 3 + 2]);

    float sx = qx * inv_res;
    float sy = qy * inv_res;
    float sz = qz * inv_res;
    float fxf = floorf(sx), fyf = floorf(sy), fzf = floorf(sz);
    float ax = sx - fxf, ay = sy - fyf, az = sz - fzf;     // fracs
    float bx = 1.0f - ax, by = 1.0f - ay, bz = 1.0f - az;

    // This lane's corner (OFFSETS ordering: [x,y,z] = bits 2,1,0 of lane8).
    int ox = (lane8 >> 2) & 1, oy = (lane8 >> 1) & 1, oz = lane8 & 1;
    unsigned hoff = (ox ? P0() : 0u) + (oy ? P1() : 0u) + (oz ? P2() : 0u);

    unsigned hb = (unsigned)(int)fxf * P0() + (unsigned)(int)fyf * P1()
                + (unsigned)(int)fzf * P2();
    int v = __ldg(&h2v[(hb + hoff) & TMASK]);   // one random lookup per lane

    float4 acc = make_float4(0.f, 0.f, 0.f, 0.f);
    const int srcbase = lane16 & 8;   // stay within this level's half-group

    // Per corner c: one shfl serves both halves; each 8-lane half issues one
    // coalesced 128B row load; FMA into this lane's chunk accumulator.
#pragma unroll
    for (int c = 0; c < 8; ++c) {
        int vc = __shfl_sync(0xffffffffu, v, srcbase | c, 16);
        float wc = (((c >> 2) & 1) ? ax : bx) *
                   (((c >> 1) & 1) ? ay : by) *
                   (((c     ) & 1) ? az : bz);
        if (vc >= 0) {
            float4 f = __ldg(reinterpret_cast<const float4*>(
                                 feats + (size_t)vc * 32) + lane8);
            acc.x = fmaf(wc, f.x, acc.x);
            acc.y = fmaf(wc, f.y, acc.y);
            acc.z = fmaf(wc, f.z, acc.z);
            acc.w = fmaf(wc, f.w, acc.w);
        }
    }

    // out row: 64 floats at out[qi*64]; level lvl chunk +lvl*32 + lane8*4.
    reinterpret_cast<float4*>(out)[(size_t)qi * 16 + lane16] = acc;
}

extern "C" void kernel_launch(void* const* d_in, const int* in_sizes, int n_in,
                              void* d_out, int out_size)
{
    const float* qpts   = (const float*)d_in[0];
    const float* feats0 = (const float*)d_in[1];
    const float* feats1 = (const float*)d_in[2];
    const int*   h2v0   = (const int*)d_in[3];
    const int*   h2v1   = (const int*)d_in[4];
    float* out = (float*)d_out;

    int M = in_sizes[0] / 3;           // 500000
    long long total = 16LL * M;        // 16 lanes per query
    int block = 256;
    int grid = (int)((total + block - 1) / block);
    voxel_hash_kernel<<<grid, block>>>(qpts, feats0, feats1, h2v0, h2v1, out, M);
}

// round 7
// speedup vs baseline: 1.0546x; 1.0546x over previous
#include <cuda_runtime.h>
#include <cstdint>

// VoxelHashTable: 2-level voxel hash trilinear interpolation.
// 16 lanes per QUERY: lane k = (level = k>>3, chunk = k&7). NO shuffles:
// every lane computes all 8 corner hashes for its level and issues 8 h2v
// loads at group-identical addresses (L1 broadcast => same wavefront count
// as one-lookup+shfl, but MLP=8 and no warp-wide sync point).
// Gathers: 8 lanes x 16B = one 128B feats row = 1 coalesced wavefront.
//
// Inputs (metadata order):
//   d_in[0] query_pts : float32 (M*3)
//   d_in[1] feats0    : float32 (n0*32)
//   d_in[2] feats1    : float32 (n1*32)
//   d_in[3] h2v0      : int32   (2^20)
//   d_in[4] h2v1      : int32   (2^20)
// Output: float32 (M*64) = concat(level0, level1)

#define TSIZE 1048576u
#define TMASK (TSIZE - 1u)

#define PR0 (73856093u % TSIZE)
#define PR1 (19349669u % TSIZE)
#define PR2 (83492791u % TSIZE)

__global__ void
voxel_hash_kernel(const float* __restrict__ qpts,
                  const float* __restrict__ feats0,
                  const float* __restrict__ feats1,
                  const int*   __restrict__ h2v0,
                  const int*   __restrict__ h2v1,
                  float*       __restrict__ out,
                  int M)
{
    int t      = blockIdx.x * blockDim.x + threadIdx.x;
    int qi     = t >> 4;          // query id; grid divides exactly
    int lane16 = t & 15;
    int lane8  = lane16 & 7;      // feature-chunk id
    int lvl    = lane16 >> 3;     // level id

    const float inv_res            = lvl ? (1.0f / 0.24f) : (1.0f / 0.12f);
    const float* __restrict__ feats = lvl ? feats1 : feats0;
    const int*   __restrict__ h2v   = lvl ? h2v1   : h2v0;

    float qx = __ldg(&qpts[qi * 3 + 0]);
    float qy = __ldg(&qpts[qi * 3 + 1]);
    float qz = __ldg(&qpts[qi * 3 + 2]);

    float sx = qx * inv_res;
    float sy = qy * inv_res;
    float sz = qz * inv_res;
    float fxf = floorf(sx), fyf = floorf(sy), fzf = floorf(sz);
    float ax = sx - fxf, ay = sy - fyf, az = sz - fzf;     // fracs
    float bx = 1.0f - ax, by = 1.0f - ay, bz = 1.0f - az;

    unsigned hb = (unsigned)(int)fxf * PR0 + (unsigned)(int)fyf * PR1
                + (unsigned)(int)fzf * PR2;

    // All 8 corner lookups, issued back-to-back (MLP = 8). Within each
    // 8-lane group the addresses are identical -> L1 broadcast, so a warp's
    // LDG touches only 4 distinct lines (2 queries x 2 levels).
    // Corner c: offsets [x,y,z] = bits [2,1,0] (OFFSETS row ordering).
    int v[8];
#pragma unroll
    for (int c = 0; c < 8; ++c) {
        const unsigned hoff = (((c >> 2) & 1) ? PR0 : 0u)
                            + (((c >> 1) & 1) ? PR1 : 0u)
                            + (((c     ) & 1) ? PR2 : 0u);
        v[c] = __ldg(&h2v[(hb + hoff) & TMASK]);
    }

    float4 acc = make_float4(0.f, 0.f, 0.f, 0.f);

#pragma unroll
    for (int c = 0; c < 8; ++c) {
        float wc = (((c >> 2) & 1) ? ax : bx) *
                   (((c >> 1) & 1) ? ay : by) *
                   (((c     ) & 1) ? az : bz);
        if (v[c] >= 0) {
            // 8 lanes * 16B = one full 128B feats row, 1 wavefront.
            float4 f = __ldg(reinterpret_cast<const float4*>(
                                 feats + (size_t)v[c] * 32) + lane8);
            acc.x = fmaf(wc, f.x, acc.x);
            acc.y = fmaf(wc, f.y, acc.y);
            acc.z = fmaf(wc, f.z, acc.z);
            acc.w = fmaf(wc, f.w, acc.w);
        }
    }

    // out row: 64 floats at out[qi*64]; this lane's chunk at +lane16*4.
    reinterpret_cast<float4*>(out)[(size_t)qi * 16 + lane16] = acc;
}

extern "C" void kernel_launch(void* const* d_in, const int* in_sizes, int n_in,
                              void* d_out, int out_size)
{
    const float* qpts   = (const float*)d_in[0];
    const float* feats0 = (const float*)d_in[1];
    const float* feats1 = (const float*)d_in[2];
    const int*   h2v0   = (const int*)d_in[3];
    const int*   h2v1   = (const int*)d_in[4];
    float* out = (float*)d_out;

    int M = in_sizes[0] / 3;           // 500000
    long long total = 16LL * M;        // 16 lanes per query
    int block = 256;
    int grid = (int)((total + block - 1) / block);
    voxel_hash_kernel<<<grid, block>>>(qpts, feats0, feats1, h2v0, h2v1, out, M);
}